// round 2
// baseline (speedup 1.0000x reference)
#include <cuda_runtime.h>

typedef unsigned long long u64;

#define NPTS  131072
#define BSEG  32
#define SEGSZ 4096
#define HCH   128
#define OCH   256
#define EPSV  1e-7f
#define NSM   148

// ---------------- scratch (no allocation allowed -> device globals) ----------------
__device__ float g_h1[(size_t)NPTS * HCH * 3];
__device__ float g_h2[(size_t)NPTS * HCH * 3];
__device__ float g_h4[(size_t)NPTS * OCH * 3];
__device__ u64   g_seg1[BSEG * HCH];
__device__ u64   g_seg2[BSEG * OCH];
__device__ float g_Wc1[HCH * HCH];
__device__ float g_Wc2[OCH * OCH];
__device__ float g_g3[BSEG * HCH * 3];
__device__ float g_pool1[BSEG * HCH * 3];
__device__ float g_g5[BSEG * OCH * 3];
__device__ float g_P2[BSEG * OCH * 3];
__device__ float g_D2[BSEG * OCH * 3];

// ---------------- helpers ----------------
__device__ __forceinline__ u64 fma2(u64 a, u64 b, u64 c) {
    u64 d;
    asm("fma.rn.f32x2 %0, %1, %2, %3;" : "=l"(d) : "l"(a), "l"(b), "l"(c));
    return d;
}
__device__ __forceinline__ u64 pack2(float a, float b) {
    u64 r;
    asm("mov.b64 %0, {%1, %2};" : "=l"(r) : "f"(a), "f"(b));
    return r;
}
__device__ __forceinline__ float2 unpack2(u64 v) {
    float2 r;
    asm("mov.b64 {%0, %1}, %2;" : "=f"(r.x), "=f"(r.y) : "l"(v));
    return r;
}
__device__ __forceinline__ unsigned fsortkey(float f) {
    unsigned u = __float_as_uint(f);
    return (u & 0x80000000u) ? ~u : (u | 0x80000000u);
}

// ---------------- small kernels ----------------
__global__ void combine_w_kernel(const float* __restrict__ A, const float* __restrict__ Bm,
                                 float* __restrict__ Cm, int D) {
    int idx = blockIdx.x * blockDim.x + threadIdx.x;
    if (idx >= D * D) return;
    int c = idx / D, k = idx - c * D;
    float acc = 0.f;
    for (int j = 0; j < D; j++) acc = fmaf(A[c * D + j], Bm[j * D + k], acc);
    Cm[idx] = acc;
}

__global__ void zero_seg_kernel() {
    int i = blockIdx.x * blockDim.x + threadIdx.x;
    if (i < BSEG * HCH) g_seg1[i] = 0ull;
    if (i < BSEG * OCH) g_seg2[i] = 0ull;
}

// g[s][c][:] = sum_k W[c][k] * h[winner(s,c)][k][:]
__global__ void gather_kernel(const u64* __restrict__ segK, const float* __restrict__ h,
                              const float* __restrict__ W, float* __restrict__ g, int C, int K) {
    int s = blockIdx.x, c = threadIdx.x;
    u64 key = segK[s * C + c];
    int n = (int)(0xFFFFFFFFu - (unsigned)(key & 0xFFFFFFFFull));
    const float* hn = &h[(size_t)n * K * 3];
    const float* wr = &W[(size_t)c * K];
    float a0 = 0.f, a1 = 0.f, a2 = 0.f;
    for (int k = 0; k < K; k++) {
        float w = wr[k];
        a0 = fmaf(w, hn[k * 3 + 0], a0);
        a1 = fmaf(w, hn[k * 3 + 1], a1);
        a2 = fmaf(w, hn[k * 3 + 2], a2);
    }
    float* gp = &g[(size_t)(s * C + c) * 3];
    gp[0] = a0; gp[1] = a1; gp[2] = a2;
}

// VNLeakyReLU (ns=0) on [BSEG, C, 3]
__global__ void vn_lrelu_small_kernel(const float* __restrict__ g, const float* __restrict__ W,
                                      float* __restrict__ out, int C) {
    extern __shared__ float sg[];
    int s = blockIdx.x, c = threadIdx.x;
    for (int i = c; i < C * 3; i += blockDim.x) sg[i] = g[(size_t)s * C * 3 + i];
    __syncthreads();
    const float* wr = &W[(size_t)c * C];
    float d0 = 0.f, d1 = 0.f, d2 = 0.f;
    for (int k = 0; k < C; k++) {
        float w = wr[k];
        d0 = fmaf(w, sg[k * 3 + 0], d0);
        d1 = fmaf(w, sg[k * 3 + 1], d1);
        d2 = fmaf(w, sg[k * 3 + 2], d2);
    }
    float x0 = sg[c * 3 + 0], x1 = sg[c * 3 + 1], x2 = sg[c * 3 + 2];
    float dot = x0 * d0 + x1 * d1 + x2 * d2;
    float dn  = d0 * d0 + d1 * d1 + d2 * d2;
    float t = (dot >= 0.f) ? 0.f : dot / (dn + EPSV);
    float* op = &out[(size_t)(s * C + c) * 3];
    op[0] = x0 - t * d0; op[1] = x1 - t * d1; op[2] = x2 - t * d2;
}

// P2[s][o][:] = W4f[o][128:256] @ pool[s];  D2 likewise with W4d
__global__ void seg_bias_kernel(const float* __restrict__ pool, const float* __restrict__ W4f,
                                const float* __restrict__ W4d) {
    __shared__ float sp[HCH * 3];
    int s = blockIdx.x, o = threadIdx.x;
    for (int i = o; i < HCH * 3; i += blockDim.x) sp[i] = pool[(size_t)s * HCH * 3 + i];
    __syncthreads();
    float f0 = 0.f, f1 = 0.f, f2 = 0.f, e0 = 0.f, e1 = 0.f, e2 = 0.f;
    for (int k = 0; k < HCH; k++) {
        float wf = W4f[(size_t)o * OCH + HCH + k];
        float wd = W4d[(size_t)o * OCH + HCH + k];
        float s0 = sp[k * 3 + 0], s1 = sp[k * 3 + 1], s2 = sp[k * 3 + 2];
        f0 = fmaf(wf, s0, f0); f1 = fmaf(wf, s1, f1); f2 = fmaf(wf, s2, f2);
        e0 = fmaf(wd, s0, e0); e1 = fmaf(wd, s1, e1); e2 = fmaf(wd, s2, e2);
    }
    float* pp = &g_P2[(size_t)(s * OCH + o) * 3];
    float* dp = &g_D2[(size_t)(s * OCH + o) * 3];
    pp[0] = f0; pp[1] = f1; pp[2] = f2;
    dp[0] = e0; dp[1] = e1; dp[2] = e2;
}

// ---------------- fused VNLinearLeakyReLU GEMM ----------------
// 32 points/tile, CT channels/block (offset blockIdx.y*CT), CPT channels/thread.
// y = lrelu(Wf x (+pb[seg]), Wd x (+db[seg]))
template <int K, int CT, int CPT>
__global__ void __launch_bounds__(32 * (CT / CPT))
vn_lrelu_kernel(const float* __restrict__ x, const float* __restrict__ Wf,
                const float* __restrict__ Wd, int ws, float* __restrict__ y, int ystride,
                const float* __restrict__ pb, const float* __restrict__ db,
                const int* __restrict__ segids, int ntiles) {
    constexpr int NP  = CPT / 2;
    constexpr int WST = CT + 4;
    constexpr int F   = K * 3;
    extern __shared__ __align__(16) float sm[];
    float* sWf = sm;
    float* sWd = sm + K * WST;
    float* xs  = sm + 2 * K * WST;  // [F][33] transposed tile

    const int nthr = 32 * (CT / CPT);
    const int tid  = threadIdx.y * 32 + threadIdx.x;
    const int c0   = blockIdx.y * CT;
    const int pt   = threadIdx.x, cg = threadIdx.y;

    for (int idx = tid; idx < CT * K; idx += nthr) {
        int c = idx / K, k = idx - c * K;
        sWf[k * WST + c] = Wf[(size_t)(c0 + c) * ws + k];
        sWd[k * WST + c] = Wd[(size_t)(c0 + c) * ws + k];
    }
    __syncthreads();

    for (int tile = blockIdx.x; tile < ntiles; tile += gridDim.x) {
        int base = tile * 32;
        for (int idx = tid; idx < 32 * F; idx += nthr) {
            int p = idx / F, f = idx - p * F;
            xs[f * 33 + p] = x[(size_t)(base + p) * F + f];
        }
        __syncthreads();

        u64 accP[NP][3], accD[NP][3];
#pragma unroll
        for (int p = 0; p < NP; p++)
#pragma unroll
            for (int i = 0; i < 3; i++) { accP[p][i] = 0ull; accD[p][i] = 0ull; }

#pragma unroll 4
        for (int k = 0; k < K; k++) {
            float v0 = xs[(k * 3 + 0) * 33 + pt];
            float v1 = xs[(k * 3 + 1) * 33 + pt];
            float v2 = xs[(k * 3 + 2) * 33 + pt];
            u64 xx0 = pack2(v0, v0), xx1 = pack2(v1, v1), xx2 = pack2(v2, v2);
            const u64* wfp = reinterpret_cast<const u64*>(&sWf[k * WST + cg * CPT]);
            const u64* wdp = reinterpret_cast<const u64*>(&sWd[k * WST + cg * CPT]);
#pragma unroll
            for (int p = 0; p < NP; p++) {
                u64 wf = wfp[p], wd = wdp[p];
                accP[p][0] = fma2(wf, xx0, accP[p][0]);
                accP[p][1] = fma2(wf, xx1, accP[p][1]);
                accP[p][2] = fma2(wf, xx2, accP[p][2]);
                accD[p][0] = fma2(wd, xx0, accD[p][0]);
                accD[p][1] = fma2(wd, xx1, accD[p][1]);
                accD[p][2] = fma2(wd, xx2, accD[p][2]);
            }
        }

        int n = base + pt;
        int s = (pb != nullptr) ? segids[n] : 0;
        float4 outq[(CPT * 3) / 4];
        float* outv = reinterpret_cast<float*>(outq);
#pragma unroll
        for (int p = 0; p < NP; p++) {
            float2 P0 = unpack2(accP[p][0]), P1 = unpack2(accP[p][1]), P2v = unpack2(accP[p][2]);
            float2 D0 = unpack2(accD[p][0]), D1 = unpack2(accD[p][1]), D2v = unpack2(accD[p][2]);
#pragma unroll
            for (int h = 0; h < 2; h++) {
                float p0 = h ? P0.y : P0.x, p1 = h ? P1.y : P1.x, p2 = h ? P2v.y : P2v.x;
                float d0 = h ? D0.y : D0.x, d1 = h ? D1.y : D1.x, d2 = h ? D2v.y : D2v.x;
                int cl = 2 * p + h;
                if (pb != nullptr) {
                    int boff = (s * ystride + c0 + cg * CPT + cl) * 3;
                    p0 += pb[boff + 0]; p1 += pb[boff + 1]; p2 += pb[boff + 2];
                    d0 += db[boff + 0]; d1 += db[boff + 1]; d2 += db[boff + 2];
                }
                float dot = p0 * d0 + p1 * d1 + p2 * d2;
                float dn  = d0 * d0 + d1 * d1 + d2 * d2;
                float t = (dot >= 0.f) ? 0.f : dot / (dn + EPSV);
                outv[cl * 3 + 0] = p0 - t * d0;
                outv[cl * 3 + 1] = p1 - t * d1;
                outv[cl * 3 + 2] = p2 - t * d2;
            }
        }
        float4* yq = reinterpret_cast<float4*>(&y[((size_t)n * ystride + c0 + cg * CPT) * 3]);
#pragma unroll
        for (int q = 0; q < (CPT * 3) / 4; q++) yq[q] = outq[q];
        __syncthreads();
    }
}

// ---------------- fused dot + segment argmax ----------------
// dot[n,c] = <(Wa x)[n,c,:], (Wc x)[n,c,:]>, packed-key atomicMax per (segment, channel)
template <int K, int CT, int CPT>
__global__ void __launch_bounds__(32 * (CT / CPT))
vn_dot_argmax_kernel(const float* __restrict__ x, const float* __restrict__ Wa,
                     const float* __restrict__ Wc, int Ctot,
                     const int* __restrict__ segids, u64* __restrict__ segK, int ntiles) {
    constexpr int NP  = CPT / 2;
    constexpr int WST = CT + 4;
    constexpr int F   = K * 3;
    extern __shared__ __align__(16) float sm[];
    float* sWa = sm;
    float* sWc = sm + K * WST;
    float* xs  = sm + 2 * K * WST;

    const int nthr = 32 * (CT / CPT);
    const int tid  = threadIdx.y * 32 + threadIdx.x;
    const int c0   = blockIdx.y * CT;
    const int pt   = threadIdx.x, cg = threadIdx.y;

    for (int idx = tid; idx < CT * K; idx += nthr) {
        int c = idx / K, k = idx - c * K;
        sWa[k * WST + c] = Wa[(size_t)(c0 + c) * K + k];
        sWc[k * WST + c] = Wc[(size_t)(c0 + c) * K + k];
    }
    __syncthreads();

    for (int tile = blockIdx.x; tile < ntiles; tile += gridDim.x) {
        int base = tile * 32;
        int s = segids[base];  // SEGSZ % 32 == 0 -> tile never crosses a segment
        for (int idx = tid; idx < 32 * F; idx += nthr) {
            int p = idx / F, f = idx - p * F;
            xs[f * 33 + p] = x[(size_t)(base + p) * F + f];
        }
        __syncthreads();

        u64 accA[NP][3], accC[NP][3];
#pragma unroll
        for (int p = 0; p < NP; p++)
#pragma unroll
            for (int i = 0; i < 3; i++) { accA[p][i] = 0ull; accC[p][i] = 0ull; }

#pragma unroll 4
        for (int k = 0; k < K; k++) {
            float v0 = xs[(k * 3 + 0) * 33 + pt];
            float v1 = xs[(k * 3 + 1) * 33 + pt];
            float v2 = xs[(k * 3 + 2) * 33 + pt];
            u64 xx0 = pack2(v0, v0), xx1 = pack2(v1, v1), xx2 = pack2(v2, v2);
            const u64* wap = reinterpret_cast<const u64*>(&sWa[k * WST + cg * CPT]);
            const u64* wcp = reinterpret_cast<const u64*>(&sWc[k * WST + cg * CPT]);
#pragma unroll
            for (int p = 0; p < NP; p++) {
                u64 wa = wap[p], wc = wcp[p];
                accA[p][0] = fma2(wa, xx0, accA[p][0]);
                accA[p][1] = fma2(wa, xx1, accA[p][1]);
                accA[p][2] = fma2(wa, xx2, accA[p][2]);
                accC[p][0] = fma2(wc, xx0, accC[p][0]);
                accC[p][1] = fma2(wc, xx1, accC[p][1]);
                accC[p][2] = fma2(wc, xx2, accC[p][2]);
            }
        }

        int n = base + pt;
        u64 key[CPT];
#pragma unroll
        for (int p = 0; p < NP; p++) {
            float2 A0 = unpack2(accA[p][0]), A1 = unpack2(accA[p][1]), A2 = unpack2(accA[p][2]);
            float2 C0 = unpack2(accC[p][0]), C1 = unpack2(accC[p][1]), C2 = unpack2(accC[p][2]);
#pragma unroll
            for (int h = 0; h < 2; h++) {
                float a0 = h ? A0.y : A0.x, a1 = h ? A1.y : A1.x, a2 = h ? A2.y : A2.x;
                float q0 = h ? C0.y : C0.x, q1 = h ? C1.y : C1.x, q2 = h ? C2.y : C2.x;
                float dot = a0 * q0 + a1 * q1 + a2 * q2;
                key[2 * p + h] = ((u64)fsortkey(dot) << 32) |
                                 (u64)(0xFFFFFFFFu - (unsigned)n);
            }
        }
#pragma unroll
        for (int off = 16; off > 0; off >>= 1) {
#pragma unroll
            for (int j = 0; j < CPT; j++) {
                u64 o = __shfl_xor_sync(0xFFFFFFFFu, key[j], off);
                if (o > key[j]) key[j] = o;
            }
        }
        if (threadIdx.x == 0) {
#pragma unroll
            for (int j = 0; j < CPT; j++)
                atomicMax(&segK[s * Ctot + c0 + cg * CPT + j], key[j]);
        }
        __syncthreads();
    }
}

// ---------------- launch ----------------
extern "C" void kernel_launch(void* const* d_in, const int* in_sizes, int n_in,
                              void* d_out, int out_size) {
    const float* pos = (const float*)d_in[0];
    const int*   seg = (const int*)d_in[1];
    const float* W1f = (const float*)d_in[2];
    const float* W1d = (const float*)d_in[3];
    const float* W2f = (const float*)d_in[4];
    const float* W2d = (const float*)d_in[5];
    const float* W3  = (const float*)d_in[6];
    const float* Wd1 = (const float*)d_in[7];
    const float* Wr3 = (const float*)d_in[8];
    const float* W4f = (const float*)d_in[9];
    const float* W4d = (const float*)d_in[10];
    const float* W5  = (const float*)d_in[11];
    const float* Wd2 = (const float*)d_in[12];
    const float* Wr5 = (const float*)d_in[13];
    float* out = (float*)d_out;

    float *p_h1, *p_h2, *p_h4, *p_Wc1, *p_Wc2, *p_g3, *p_pool1, *p_g5, *p_P2, *p_D2;
    u64 *p_seg1, *p_seg2;
    cudaGetSymbolAddress((void**)&p_h1, g_h1);
    cudaGetSymbolAddress((void**)&p_h2, g_h2);
    cudaGetSymbolAddress((void**)&p_h4, g_h4);
    cudaGetSymbolAddress((void**)&p_Wc1, g_Wc1);
    cudaGetSymbolAddress((void**)&p_Wc2, g_Wc2);
    cudaGetSymbolAddress((void**)&p_g3, g_g3);
    cudaGetSymbolAddress((void**)&p_pool1, g_pool1);
    cudaGetSymbolAddress((void**)&p_g5, g_g5);
    cudaGetSymbolAddress((void**)&p_P2, g_P2);
    cudaGetSymbolAddress((void**)&p_D2, g_D2);
    cudaGetSymbolAddress((void**)&p_seg1, g_seg1);
    cudaGetSymbolAddress((void**)&p_seg2, g_seg2);

    const int SM_LRELU = (2 * 128 * 68 + 384 * 33) * 4;  // 120320
    const int SM_DOT_E = (2 * 256 * 36 + 768 * 33) * 4;  // 175104

    cudaFuncSetAttribute(vn_lrelu_kernel<128, 64, 8>,
                         cudaFuncAttributeMaxDynamicSharedMemorySize, SM_LRELU);
    cudaFuncSetAttribute(vn_dot_argmax_kernel<128, 64, 8>,
                         cudaFuncAttributeMaxDynamicSharedMemorySize, SM_LRELU);
    cudaFuncSetAttribute(vn_dot_argmax_kernel<256, 32, 4>,
                         cudaFuncAttributeMaxDynamicSharedMemorySize, SM_DOT_E);

    const int ntiles = NPTS / 32;  // 4096
    dim3 blk(32, 8);

    // folded weights + clear argmax keys
    combine_w_kernel<<<(HCH * HCH + 255) / 256, 256>>>(Wd1, W3, p_Wc1, HCH);
    combine_w_kernel<<<(OCH * OCH + 255) / 256, 256>>>(Wd2, W5, p_Wc2, OCH);
    zero_seg_kernel<<<(BSEG * OCH + 255) / 256, 256>>>();

    // vn1: pos -> h1
    vn_lrelu_kernel<128, 64, 8><<<dim3(NSM, 2), blk, SM_LRELU>>>(
        pos, W1f, W1d, 128, p_h1, 128, nullptr, nullptr, nullptr, ntiles);
    // vn2: h1 -> h2
    vn_lrelu_kernel<128, 64, 8><<<dim3(NSM, 2), blk, SM_LRELU>>>(
        p_h1, W2f, W2d, 128, p_h2, 128, nullptr, nullptr, nullptr, ntiles);
    // vn3 + Wd1 dot + segment argmax (no [N,128,3] intermediate)
    vn_dot_argmax_kernel<128, 64, 8><<<dim3(NSM, 2), blk, SM_LRELU>>>(
        p_h2, W3, p_Wc1, 128, seg, p_seg1, ntiles);
    // gather winners -> g3; relu3 -> pool1; per-segment vn4 biases
    gather_kernel<<<BSEG, HCH>>>(p_seg1, p_h2, W3, p_g3, HCH, HCH);
    vn_lrelu_small_kernel<<<BSEG, HCH, HCH * 3 * 4>>>(p_g3, Wr3, p_pool1, HCH);
    seg_bias_kernel<<<BSEG, OCH>>>(p_pool1, W4f, W4d);
    // vn4 on concat (K halved via segment bias): pos -> h4 [N,256,3]
    vn_lrelu_kernel<128, 64, 8><<<dim3(NSM, 4), blk, SM_LRELU>>>(
        pos, W4f, W4d, 256, p_h4, 256, p_P2, p_D2, seg, ntiles);
    // vn5 + Wd2 dot + segment argmax
    vn_dot_argmax_kernel<256, 32, 4><<<dim3(NSM, 8), blk, SM_DOT_E>>>(
        p_h4, W5, p_Wc2, 256, seg, p_seg2, ntiles);
    // gather winners -> g5; relu5 -> out
    gather_kernel<<<BSEG, OCH>>>(p_seg2, p_h4, W5, p_g5, OCH, OCH);
    vn_lrelu_small_kernel<<<BSEG, OCH, OCH * 3 * 4>>>(p_g5, Wr5, out, OCH);
}

// round 5
// speedup vs baseline: 1.1998x; 1.1998x over previous
// R4: byte-identical to R2/R3 (two consecutive broker failures; third attempt for attribution)
#include <cuda_runtime.h>

typedef unsigned long long u64;

#define NPTS  131072
#define BSEG  32
#define SEGSZ 4096
#define HCH   128
#define OCH   256
#define EPSV  1e-7f

// ---------------- scratch (no allocation allowed -> device globals) ----------------
__device__ float g_h1[(size_t)NPTS * HCH * 3];
__device__ float g_h2[(size_t)NPTS * HCH * 3];
__device__ float g_h4[(size_t)NPTS * OCH * 3];
__device__ u64   g_seg1[BSEG * HCH];
__device__ u64   g_seg2[BSEG * OCH];
__device__ float g_Wc1[HCH * HCH];
__device__ float g_Wc2[OCH * OCH];
__device__ float g_g3[BSEG * HCH * 3];
__device__ float g_pool1[BSEG * HCH * 3];
__device__ float g_g5[BSEG * OCH * 3];
__device__ float g_P2[BSEG * OCH * 3];
__device__ float g_D2[BSEG * OCH * 3];

// ---------------- helpers ----------------
__device__ __forceinline__ u64 fma2(u64 a, u64 b, u64 c) {
    u64 d;
    asm("fma.rn.f32x2 %0, %1, %2, %3;" : "=l"(d) : "l"(a), "l"(b), "l"(c));
    return d;
}
__device__ __forceinline__ u64 pack2(float a, float b) {
    u64 r;
    asm("mov.b64 %0, {%1, %2};" : "=l"(r) : "f"(a), "f"(b));
    return r;
}
__device__ __forceinline__ float2 unpack2(u64 v) {
    float2 r;
    asm("mov.b64 {%0, %1}, %2;" : "=f"(r.x), "=f"(r.y) : "l"(v));
    return r;
}
__device__ __forceinline__ unsigned fsortkey(float f) {
    unsigned u = __float_as_uint(f);
    return (u & 0x80000000u) ? ~u : (u | 0x80000000u);
}

// ---------------- small kernels ----------------
__global__ void combine_w_kernel(const float* __restrict__ A, const float* __restrict__ Bm,
                                 float* __restrict__ Cm, int D) {
    int idx = blockIdx.x * blockDim.x + threadIdx.x;
    if (idx >= D * D) return;
    int c = idx / D, k = idx - c * D;
    float acc = 0.f;
    for (int j = 0; j < D; j++) acc = fmaf(A[c * D + j], Bm[j * D + k], acc);
    Cm[idx] = acc;
}

__global__ void zero_seg_kernel() {
    int i = blockIdx.x * blockDim.x + threadIdx.x;
    if (i < BSEG * HCH) g_seg1[i] = 0ull;
    if (i < BSEG * OCH) g_seg2[i] = 0ull;
}

__global__ void gather_kernel(const u64* __restrict__ segK, const float* __restrict__ h,
                              const float* __restrict__ W, float* __restrict__ g, int C, int K) {
    int s = blockIdx.x, c = threadIdx.x;
    u64 key = segK[s * C + c];
    int n = (int)(0xFFFFFFFFu - (unsigned)(key & 0xFFFFFFFFull));
    const float* hn = &h[(size_t)n * K * 3];
    const float* wr = &W[(size_t)c * K];
    float a0 = 0.f, a1 = 0.f, a2 = 0.f;
    for (int k = 0; k < K; k++) {
        float w = wr[k];
        a0 = fmaf(w, hn[k * 3 + 0], a0);
        a1 = fmaf(w, hn[k * 3 + 1], a1);
        a2 = fmaf(w, hn[k * 3 + 2], a2);
    }
    float* gp = &g[(size_t)(s * C + c) * 3];
    gp[0] = a0; gp[1] = a1; gp[2] = a2;
}

__global__ void vn_lrelu_small_kernel(const float* __restrict__ g, const float* __restrict__ W,
                                      float* __restrict__ out, int C) {
    extern __shared__ float sg[];
    int s = blockIdx.x, c = threadIdx.x;
    for (int i = c; i < C * 3; i += blockDim.x) sg[i] = g[(size_t)s * C * 3 + i];
    __syncthreads();
    const float* wr = &W[(size_t)c * C];
    float d0 = 0.f, d1 = 0.f, d2 = 0.f;
    for (int k = 0; k < C; k++) {
        float w = wr[k];
        d0 = fmaf(w, sg[k * 3 + 0], d0);
        d1 = fmaf(w, sg[k * 3 + 1], d1);
        d2 = fmaf(w, sg[k * 3 + 2], d2);
    }
    float x0 = sg[c * 3 + 0], x1 = sg[c * 3 + 1], x2 = sg[c * 3 + 2];
    float dot = x0 * d0 + x1 * d1 + x2 * d2;
    float dn  = d0 * d0 + d1 * d1 + d2 * d2;
    float t = (dot >= 0.f) ? 0.f : dot / (dn + EPSV);
    float* op = &out[(size_t)(s * C + c) * 3];
    op[0] = x0 - t * d0; op[1] = x1 - t * d1; op[2] = x2 - t * d2;
}

__global__ void seg_bias_kernel(const float* __restrict__ pool, const float* __restrict__ W4f,
                                const float* __restrict__ W4d) {
    __shared__ float sp[HCH * 3];
    int s = blockIdx.x, o = threadIdx.x;
    for (int i = o; i < HCH * 3; i += blockDim.x) sp[i] = pool[(size_t)s * HCH * 3 + i];
    __syncthreads();
    float f0 = 0.f, f1 = 0.f, f2 = 0.f, e0 = 0.f, e1 = 0.f, e2 = 0.f;
    for (int k = 0; k < HCH; k++) {
        float wf = W4f[(size_t)o * OCH + HCH + k];
        float wd = W4d[(size_t)o * OCH + HCH + k];
        float s0 = sp[k * 3 + 0], s1 = sp[k * 3 + 1], s2 = sp[k * 3 + 2];
        f0 = fmaf(wf, s0, f0); f1 = fmaf(wf, s1, f1); f2 = fmaf(wf, s2, f2);
        e0 = fmaf(wd, s0, e0); e1 = fmaf(wd, s1, e1); e2 = fmaf(wd, s2, e2);
    }
    float* pp = &g_P2[(size_t)(s * OCH + o) * 3];
    float* dp = &g_D2[(size_t)(s * OCH + o) * 3];
    pp[0] = f0; pp[1] = f1; pp[2] = f2;
    dp[0] = e0; dp[1] = e1; dp[2] = e2;
}

// ---------------- shared staging helpers ----------------
template <int K, int CT, int WST>
__device__ __forceinline__ void stage_weights(float* sW, const float* __restrict__ W,
                                              int ws, int c0, int tid, int nthr) {
    constexpr int K4 = K / 4;
    for (int idx = tid; idx < CT * K4; idx += nthr) {
        int c = idx / K4, k4 = idx - c * K4;
        float4 v = *reinterpret_cast<const float4*>(&W[(size_t)(c0 + c) * ws + 4 * k4]);
        sW[(4 * k4 + 0) * WST + c] = v.x;
        sW[(4 * k4 + 1) * WST + c] = v.y;
        sW[(4 * k4 + 2) * WST + c] = v.z;
        sW[(4 * k4 + 3) * WST + c] = v.w;
    }
}

template <int F, int TPTS, int XS>
__device__ __forceinline__ void stage_x(float* xs, const float* __restrict__ x,
                                        int base, int tid, int nthr) {
    constexpr int F4 = F / 4;
    for (int idx = tid; idx < TPTS * F4; idx += nthr) {
        int p = idx / F4, f4 = idx - p * F4;
        float4 v = *reinterpret_cast<const float4*>(&x[(size_t)(base + p) * F + 4 * f4]);
        xs[p * XS + 4 * f4 + 0] = v.x;
        xs[p * XS + 4 * f4 + 1] = v.y;
        xs[p * XS + 4 * f4 + 2] = v.z;
        xs[p * XS + 4 * f4 + 3] = v.w;
    }
}

// ---------------- fused VNLinearLeakyReLU GEMM (2 points/thread) ----------------
template <int K, int CT, int CPT, int TPTS>
__global__ void __launch_bounds__((TPTS / 2) * (CT / CPT))
vn_lrelu2_kernel(const float* __restrict__ x, const float* __restrict__ Wf,
                 const float* __restrict__ Wd, int ws, float* __restrict__ y, int ystride,
                 const float* __restrict__ pb, const float* __restrict__ db,
                 const int* __restrict__ segids, int ntiles) {
    constexpr int PH  = TPTS / 2;
    constexpr int NP  = CPT / 2;
    constexpr int F   = 3 * K;
    constexpr int XS  = F + 1;      // odd stride -> conflict-free point-major reads
    constexpr int WST = CT + 4;
    extern __shared__ __align__(16) float sm[];
    float* sWf = sm;
    float* sWd = sm + K * WST;
    float* xs  = sm + 2 * K * WST;

    const int nthr = PH * (CT / CPT);
    const int tid  = threadIdx.y * PH + threadIdx.x;
    const int c0   = blockIdx.y * CT;
    const int ptg  = threadIdx.x, cg = threadIdx.y;

    stage_weights<K, CT, WST>(sWf, Wf, ws, c0, tid, nthr);
    stage_weights<K, CT, WST>(sWd, Wd, ws, c0, tid, nthr);
    __syncthreads();

    for (int tile = blockIdx.x; tile < ntiles; tile += gridDim.x) {
        int base = tile * TPTS;
        stage_x<F, TPTS, XS>(xs, x, base, tid, nthr);
        __syncthreads();

        u64 accP[2][NP][3], accD[2][NP][3];
#pragma unroll
        for (int pt = 0; pt < 2; pt++)
#pragma unroll
            for (int p = 0; p < NP; p++)
#pragma unroll
                for (int i = 0; i < 3; i++) { accP[pt][p][i] = 0ull; accD[pt][p][i] = 0ull; }

#pragma unroll 2
        for (int k = 0; k < K; k++) {
            const u64* wfp = reinterpret_cast<const u64*>(&sWf[k * WST + cg * CPT]);
            const u64* wdp = reinterpret_cast<const u64*>(&sWd[k * WST + cg * CPT]);
            u64 wf[NP], wd[NP];
#pragma unroll
            for (int p = 0; p < NP; p++) { wf[p] = wfp[p]; wd[p] = wdp[p]; }
#pragma unroll
            for (int pt = 0; pt < 2; pt++) {
                const float* xr = &xs[(ptg + pt * PH) * XS + 3 * k];
                u64 xx0 = pack2(xr[0], xr[0]);
                u64 xx1 = pack2(xr[1], xr[1]);
                u64 xx2 = pack2(xr[2], xr[2]);
#pragma unroll
                for (int p = 0; p < NP; p++) {
                    accP[pt][p][0] = fma2(wf[p], xx0, accP[pt][p][0]);
                    accP[pt][p][1] = fma2(wf[p], xx1, accP[pt][p][1]);
                    accP[pt][p][2] = fma2(wf[p], xx2, accP[pt][p][2]);
                    accD[pt][p][0] = fma2(wd[p], xx0, accD[pt][p][0]);
                    accD[pt][p][1] = fma2(wd[p], xx1, accD[pt][p][1]);
                    accD[pt][p][2] = fma2(wd[p], xx2, accD[pt][p][2]);
                }
            }
        }

        // bias (vn4): same segment + channels for both points of this thread
        float bias[2 * CPT * 3];
        if (pb != nullptr) {
            int s = segids[base];
            int boff = (s * ystride + c0 + cg * CPT) * 3;
#pragma unroll
            for (int q = 0; q < (CPT * 3) / 4; q++) {
                reinterpret_cast<float4*>(bias)[q] =
                    reinterpret_cast<const float4*>(&pb[boff])[q];
                reinterpret_cast<float4*>(bias + CPT * 3)[q] =
                    reinterpret_cast<const float4*>(&db[boff])[q];
            }
        }

#pragma unroll
        for (int pt = 0; pt < 2; pt++) {
            int n = base + ptg + pt * PH;
            float4 outq[(CPT * 3) / 4];
            float* outv = reinterpret_cast<float*>(outq);
#pragma unroll
            for (int p = 0; p < NP; p++) {
                float2 P0 = unpack2(accP[pt][p][0]), P1 = unpack2(accP[pt][p][1]),
                       P2v = unpack2(accP[pt][p][2]);
                float2 D0 = unpack2(accD[pt][p][0]), D1 = unpack2(accD[pt][p][1]),
                       D2v = unpack2(accD[pt][p][2]);
#pragma unroll
                for (int h = 0; h < 2; h++) {
                    float p0 = h ? P0.y : P0.x, p1 = h ? P1.y : P1.x, p2 = h ? P2v.y : P2v.x;
                    float d0 = h ? D0.y : D0.x, d1 = h ? D1.y : D1.x, d2 = h ? D2v.y : D2v.x;
                    int cl = 2 * p + h;
                    if (pb != nullptr) {
                        p0 += bias[cl * 3 + 0]; p1 += bias[cl * 3 + 1]; p2 += bias[cl * 3 + 2];
                        d0 += bias[CPT * 3 + cl * 3 + 0];
                        d1 += bias[CPT * 3 + cl * 3 + 1];
                        d2 += bias[CPT * 3 + cl * 3 + 2];
                    }
                    float dot = p0 * d0 + p1 * d1 + p2 * d2;
                    float dn  = d0 * d0 + d1 * d1 + d2 * d2;
                    float t = (dot >= 0.f) ? 0.f : dot / (dn + EPSV);
                    outv[cl * 3 + 0] = p0 - t * d0;
                    outv[cl * 3 + 1] = p1 - t * d1;
                    outv[cl * 3 + 2] = p2 - t * d2;
                }
            }
            float4* yq = reinterpret_cast<float4*>(
                &y[((size_t)n * ystride + c0 + cg * CPT) * 3]);
#pragma unroll
            for (int q = 0; q < (CPT * 3) / 4; q++) yq[q] = outq[q];
        }
        __syncthreads();
    }
}

// ---------------- fused dot + segment argmax (2 points/thread) ----------------
template <int K, int CT, int CPT, int TPTS>
__global__ void __launch_bounds__((TPTS / 2) * (CT / CPT))
vn_dot2_kernel(const float* __restrict__ x, const float* __restrict__ Wa,
               const float* __restrict__ Wc, int Ctot,
               const int* __restrict__ segids, u64* __restrict__ segK, int ntiles) {
    constexpr int PH  = TPTS / 2;
    constexpr int NP  = CPT / 2;
    constexpr int F   = 3 * K;
    constexpr int XS  = F + 1;
    constexpr int WST = CT + 4;
    extern __shared__ __align__(16) float sm[];
    float* sWa = sm;
    float* sWc = sm + K * WST;
    float* xs  = sm + 2 * K * WST;

    const int nthr = PH * (CT / CPT);
    const int tid  = threadIdx.y * PH + threadIdx.x;
    const int c0   = blockIdx.y * CT;
    const int ptg  = threadIdx.x, cg = threadIdx.y;

    stage_weights<K, CT, WST>(sWa, Wa, K, c0, tid, nthr);
    stage_weights<K, CT, WST>(sWc, Wc, K, c0, tid, nthr);
    __syncthreads();

    for (int tile = blockIdx.x; tile < ntiles; tile += gridDim.x) {
        int base = tile * TPTS;
        int s = segids[base];  // SEGSZ % TPTS == 0 -> tile inside one segment
        stage_x<F, TPTS, XS>(xs, x, base, tid, nthr);
        __syncthreads();

        u64 accA[2][NP][3], accC[2][NP][3];
#pragma unroll
        for (int pt = 0; pt < 2; pt++)
#pragma unroll
            for (int p = 0; p < NP; p++)
#pragma unroll
                for (int i = 0; i < 3; i++) { accA[pt][p][i] = 0ull; accC[pt][p][i] = 0ull; }

#pragma unroll 2
        for (int k = 0; k < K; k++) {
            const u64* wap = reinterpret_cast<const u64*>(&sWa[k * WST + cg * CPT]);
            const u64* wcp = reinterpret_cast<const u64*>(&sWc[k * WST + cg * CPT]);
            u64 wa[NP], wc[NP];
#pragma unroll
            for (int p = 0; p < NP; p++) { wa[p] = wap[p]; wc[p] = wcp[p]; }
#pragma unroll
            for (int pt = 0; pt < 2; pt++) {
                const float* xr = &xs[(ptg + pt * PH) * XS + 3 * k];
                u64 xx0 = pack2(xr[0], xr[0]);
                u64 xx1 = pack2(xr[1], xr[1]);
                u64 xx2 = pack2(xr[2], xr[2]);
#pragma unroll
                for (int p = 0; p < NP; p++) {
                    accA[pt][p][0] = fma2(wa[p], xx0, accA[pt][p][0]);
                    accA[pt][p][1] = fma2(wa[p], xx1, accA[pt][p][1]);
                    accA[pt][p][2] = fma2(wa[p], xx2, accA[pt][p][2]);
                    accC[pt][p][0] = fma2(wc[p], xx0, accC[pt][p][0]);
                    accC[pt][p][1] = fma2(wc[p], xx1, accC[pt][p][1]);
                    accC[pt][p][2] = fma2(wc[p], xx2, accC[pt][p][2]);
                }
            }
        }

        u64 key[CPT];
#pragma unroll
        for (int j = 0; j < CPT; j++) key[j] = 0ull;
#pragma unroll
        for (int pt = 0; pt < 2; pt++) {
            int n = base + ptg + pt * PH;
#pragma unroll
            for (int p = 0; p < NP; p++) {
                float2 A0 = unpack2(accA[pt][p][0]), A1 = unpack2(accA[pt][p][1]),
                       A2 = unpack2(accA[pt][p][2]);
                float2 C0 = unpack2(accC[pt][p][0]), C1 = unpack2(accC[pt][p][1]),
                       C2 = unpack2(accC[pt][p][2]);
#pragma unroll
                for (int h = 0; h < 2; h++) {
                    float a0 = h ? A0.y : A0.x, a1 = h ? A1.y : A1.x, a2 = h ? A2.y : A2.x;
                    float q0 = h ? C0.y : C0.x, q1 = h ? C1.y : C1.x, q2 = h ? C2.y : C2.x;
                    float dot = a0 * q0 + a1 * q1 + a2 * q2;
                    u64 kk = ((u64)fsortkey(dot) << 32) | (u64)(0xFFFFFFFFu - (unsigned)n);
                    if (kk > key[2 * p + h]) key[2 * p + h] = kk;
                }
            }
        }
#pragma unroll
        for (int off = PH / 2; off > 0; off >>= 1) {
#pragma unroll
            for (int j = 0; j < CPT; j++) {
                u64 o = __shfl_xor_sync(0xFFFFFFFFu, key[j], off);
                if (o > key[j]) key[j] = o;
            }
        }
        if (threadIdx.x == 0) {
#pragma unroll
            for (int j = 0; j < CPT; j++)
                atomicMax(&segK[s * Ctot + c0 + cg * CPT + j], key[j]);
        }
        __syncthreads();
    }
}

// ---------------- launch ----------------
extern "C" void kernel_launch(void* const* d_in, const int* in_sizes, int n_in,
                              void* d_out, int out_size) {
    const float* pos = (const float*)d_in[0];
    const int*   seg = (const int*)d_in[1];
    const float* W1f = (const float*)d_in[2];
    const float* W1d = (const float*)d_in[3];
    const float* W2f = (const float*)d_in[4];
    const float* W2d = (const float*)d_in[5];
    const float* W3  = (const float*)d_in[6];
    const float* Wd1 = (const float*)d_in[7];
    const float* Wr3 = (const float*)d_in[8];
    const float* W4f = (const float*)d_in[9];
    const float* W4d = (const float*)d_in[10];
    const float* W5  = (const float*)d_in[11];
    const float* Wd2 = (const float*)d_in[12];
    const float* Wr5 = (const float*)d_in[13];
    float* out = (float*)d_out;

    float *p_h1, *p_h2, *p_h4, *p_Wc1, *p_Wc2, *p_g3, *p_pool1, *p_g5, *p_P2, *p_D2;
    u64 *p_seg1, *p_seg2;
    cudaGetSymbolAddress((void**)&p_h1, g_h1);
    cudaGetSymbolAddress((void**)&p_h2, g_h2);
    cudaGetSymbolAddress((void**)&p_h4, g_h4);
    cudaGetSymbolAddress((void**)&p_Wc1, g_Wc1);
    cudaGetSymbolAddress((void**)&p_Wc2, g_Wc2);
    cudaGetSymbolAddress((void**)&p_g3, g_g3);
    cudaGetSymbolAddress((void**)&p_pool1, g_pool1);
    cudaGetSymbolAddress((void**)&p_g5, g_g5);
    cudaGetSymbolAddress((void**)&p_P2, g_P2);
    cudaGetSymbolAddress((void**)&p_D2, g_D2);
    cudaGetSymbolAddress((void**)&p_seg1, g_seg1);
    cudaGetSymbolAddress((void**)&p_seg2, g_seg2);

    // smem: weights 2*K*(CT+4) + xs TPTS*(3K+1), floats
    const int SM_128 = (2 * 128 * 68 + 64 * 385) * 4;   // 168192 (K=128, CT=64, TPTS=64)
    const int SM_256 = (2 * 256 * 36 + 32 * 769) * 4;   // 172160 (K=256, CT=32, TPTS=32)

    cudaFuncSetAttribute(vn_lrelu2_kernel<128, 64, 8, 64>,
                         cudaFuncAttributeMaxDynamicSharedMemorySize, SM_128);
    cudaFuncSetAttribute(vn_dot2_kernel<128, 64, 8, 64>,
                         cudaFuncAttributeMaxDynamicSharedMemorySize, SM_128);
    cudaFuncSetAttribute(vn_dot2_kernel<256, 32, 4, 32>,
                         cudaFuncAttributeMaxDynamicSharedMemorySize, SM_256);

    const int nt64 = NPTS / 64;  // 2048
    const int nt32 = NPTS / 32;  // 4096
    dim3 blk64(32, 8);  // 256 threads
    dim3 blk32(16, 8);  // 128 threads

    // folded weights + clear argmax keys
    combine_w_kernel<<<(HCH * HCH + 255) / 256, 256>>>(Wd1, W3, p_Wc1, HCH);
    combine_w_kernel<<<(OCH * OCH + 255) / 256, 256>>>(Wd2, W5, p_Wc2, OCH);
    zero_seg_kernel<<<(BSEG * OCH + 255) / 256, 256>>>();

    // vn1: pos -> h1
    vn_lrelu2_kernel<128, 64, 8, 64><<<dim3(74, 2), blk64, SM_128>>>(
        pos, W1f, W1d, 128, p_h1, 128, nullptr, nullptr, nullptr, nt64);
    // vn2: h1 -> h2
    vn_lrelu2_kernel<128, 64, 8, 64><<<dim3(74, 2), blk64, SM_128>>>(
        p_h1, W2f, W2d, 128, p_h2, 128, nullptr, nullptr, nullptr, nt64);
    // vn3 + Wd1 dot + segment argmax
    vn_dot2_kernel<128, 64, 8, 64><<<dim3(74, 2), blk64, SM_128>>>(
        p_h2, W3, p_Wc1, 128, seg, p_seg1, nt64);
    // gather winners -> g3; relu3 -> pool1; per-segment vn4 biases
    gather_kernel<<<BSEG, HCH>>>(p_seg1, p_h2, W3, p_g3, HCH, HCH);
    vn_lrelu_small_kernel<<<BSEG, HCH, HCH * 3 * 4>>>(p_g3, Wr3, p_pool1, HCH);
    seg_bias_kernel<<<BSEG, OCH>>>(p_pool1, W4f, W4d);
    // vn4 on concat (K halved via segment bias): pos -> h4 [N,256,3]
    vn_lrelu2_kernel<128, 64, 8, 64><<<dim3(37, 4), blk64, SM_128>>>(
        pos, W4f, W4d, 256, p_h4, 256, p_P2, p_D2, seg, nt64);
    // vn5 + Wd2 dot + segment argmax
    vn_dot2_kernel<256, 32, 4, 32><<<dim3(18, 8), blk32, SM_256>>>(
        p_h4, W5, p_Wc2, 256, seg, p_seg2, nt32);
    // gather winners -> g5; relu5 -> out
    gather_kernel<<<BSEG, OCH>>>(p_seg2, p_h4, W5, p_g5, OCH, OCH);
    vn_lrelu_small_kernel<<<BSEG, OCH, OCH * 3 * 4>>>(p_g5, Wr5, out, OCH);
}